// round 9
// baseline (speedup 1.0000x reference)
#include <cuda_runtime.h>

#define IMG 224
#define NBINS 8
#define HC 28                      // cells per dim
#define FEAT (HC * HC * NBINS)     // 6272 per image
#define SROWS 32                   // pixel rows per strip
#define NSTRIPS (IMG / SROWS)      // 7
#define LROWS (SROWS + 2)          // 34 gray rows incl vertical halo
#define SSTRIDE 232                // smem row stride (floats)
#define NTH 224
#define ROW4 (IMG / 4)             // 56 float4 per image row
#define MAXB 1024

// Gaussian (SIGMA=1, CS=8) separable: g[p][c] = GY(p)*GX(c)
#define GW3 0.0021874911f          // exp(-6.125)
#define GW2 0.0439369336f          // exp(-3.125)
#define GW1 0.3246524674f          // exp(-1.125)
#define GW0 0.8824969026f          // exp(-0.125)
// compile-time row factor
#define GY(p) (((p)==0||(p)==7) ? GW3 : ((p)==1||(p)==6) ? GW2 : ((p)==2||(p)==5) ? GW1 : GW0)

__device__ float        g_partial[MAXB * NSTRIPS];
__device__ unsigned int g_count[MAXB];          // zero-init; restored to 0 every call

__global__ void __launch_bounds__(NTH, 7)
hog_kernel(const float* __restrict__ x,
           float* __restrict__ out) {
    const int s   = blockIdx.x;     // strip (of 32 rows)
    const int b   = blockIdx.y;     // image
    const int tid = threadIdx.x;
    const int lane = tid & 31;
    const int warp = tid >> 5;

    __shared__ float sgray[LROWS * SSTRIDE];
    __shared__ float wsum[NTH / 32];
    __shared__ unsigned int s_arrive;
    __shared__ float s_inv;

    // Zero side padding: only cols 3 and 228 of each row are read as halo
    if (tid < LROWS) {
        sgray[tid * SSTRIDE + 3]   = 0.0f;
        sgray[tid * SSTRIDE + 228] = 0.0f;
    }

    // ---- Gray fill: statically unrolled, 9 predicated iterations ----
    const float* xb  = x + (size_t)b * 3 * IMG * IMG;
    const int    gr0 = s * SROWS - 1;
    {
        const int r0 = tid / ROW4;       // 0..3
        const int q  = tid - r0 * ROW4;  // 0..55
        if (s != 0 && s != NSTRIPS - 1) {
#pragma unroll
            for (int it = 0; it < 9; it++) {
                const int rr = r0 + it * 4;
                if (rr < LROWS) {
                    const float* base = xb + (gr0 + rr) * IMG + q * 4;
                    float4 r4 = *(const float4*)(base);
                    float4 g4 = *(const float4*)(base + IMG * IMG);
                    float4 b4 = *(const float4*)(base + 2 * IMG * IMG);
                    float4 o;
                    o.x = fmaf(0.2989f, r4.x, fmaf(0.587f, g4.x, 0.114f * b4.x));
                    o.y = fmaf(0.2989f, r4.y, fmaf(0.587f, g4.y, 0.114f * b4.y));
                    o.z = fmaf(0.2989f, r4.z, fmaf(0.587f, g4.z, 0.114f * b4.z));
                    o.w = fmaf(0.2989f, r4.w, fmaf(0.587f, g4.w, 0.114f * b4.w));
                    *(float4*)(sgray + rr * SSTRIDE + 4 + q * 4) = o;
                }
            }
        } else {
#pragma unroll
            for (int it = 0; it < 9; it++) {
                const int rr = r0 + it * 4;
                if (rr < LROWS) {
                    const int gr = gr0 + rr;
                    float4 o = make_float4(0.f, 0.f, 0.f, 0.f);
                    if (gr >= 0 && gr < IMG) {
                        const float* base = xb + gr * IMG + q * 4;
                        float4 r4 = *(const float4*)(base);
                        float4 g4 = *(const float4*)(base + IMG * IMG);
                        float4 b4 = *(const float4*)(base + 2 * IMG * IMG);
                        o.x = fmaf(0.2989f, r4.x, fmaf(0.587f, g4.x, 0.114f * b4.x));
                        o.y = fmaf(0.2989f, r4.y, fmaf(0.587f, g4.y, 0.114f * b4.y));
                        o.z = fmaf(0.2989f, r4.z, fmaf(0.587f, g4.z, 0.114f * b4.z));
                        o.w = fmaf(0.2989f, r4.w, fmaf(0.587f, g4.w, 0.114f * b4.w));
                    }
                    *(float4*)(sgray + rr * SSTRIDE + 4 + q * 4) = o;
                }
            }
        }
    }
    __syncthreads();

    // ---- Compute: thread = 4 adjacent columns x 8 rows = half of one cell ----
    const int cg = tid % 56;           // col group: pixel cols 4cg..4cg+3
    const int cr = tid / 56;           // cell row within strip (0..3)
    const float* base = sgray + (8 * cr) * SSTRIDE + 4 + 4 * cg;

    const bool oddh = (cg & 1) != 0;   // right half of cell
    float gxv[4];
    gxv[0] = oddh ? GW0 : GW3;
    gxv[1] = oddh ? GW1 : GW2;
    gxv[2] = oddh ? GW2 : GW1;
    gxv[3] = oddh ? GW3 : GW0;

    // Rolling horizontal-pass state: t = [1,2,1], d = [-1,0,1] per column
    float ta[4], tb[4], da[4], db[4];
    {
        float4 W = *(const float4*)(base);
        float vm = base[-1], vp = base[4];
        ta[0] = fmaf(2.f, W.x, vm + W.y);   da[0] = W.y - vm;
        ta[1] = fmaf(2.f, W.y, W.x + W.z);  da[1] = W.z - W.x;
        ta[2] = fmaf(2.f, W.z, W.y + W.w);  da[2] = W.w - W.y;
        ta[3] = fmaf(2.f, W.w, W.z + vp);   da[3] = vp - W.z;
        const float* r1 = base + SSTRIDE;
        float4 V = *(const float4*)(r1);
        float um = r1[-1], up = r1[4];
        tb[0] = fmaf(2.f, V.x, um + V.y);   db[0] = V.y - um;
        tb[1] = fmaf(2.f, V.y, V.x + V.z);  db[1] = V.z - V.x;
        tb[2] = fmaf(2.f, V.z, V.y + V.w);  db[2] = V.w - V.y;
        tb[3] = fmaf(2.f, V.w, V.z + up);   db[3] = up - V.z;
    }

    // Quadrant-fold histogram over all 32 pixels of this half-cell
    float hs[4] = {0.f, 0.f, 0.f, 0.f};
    float hd[4] = {0.f, 0.f, 0.f, 0.f};

#pragma unroll
    for (int p = 0; p < 8; p++) {
        const float* rp = base + (p + 2) * SSTRIDE;
        float4 W = *(const float4*)(rp);
        float vm = rp[-1], vp = rp[4];
        float tc[4], dc[4];
        tc[0] = fmaf(2.f, W.x, vm + W.y);   dc[0] = W.y - vm;
        tc[1] = fmaf(2.f, W.y, W.x + W.z);  dc[1] = W.z - W.x;
        tc[2] = fmaf(2.f, W.z, W.y + W.w);  dc[2] = W.w - W.y;
        tc[3] = fmaf(2.f, W.w, W.z + vp);   dc[3] = vp - W.z;

        const float gyp = GY(p);
#pragma unroll
        for (int i = 0; i < 4; i++) {
            float gx = fmaf(2.f, db[i], da[i]) + dc[i];
            float gy = tc[i] - ta[i];

            float s2 = fmaf(gy, gy, fmaf(gx, gx, 1e-6f));
            float mag;
            asm("sqrt.approx.f32 %0, %1;" : "=f"(mag) : "f"(s2));
            float w = (mag * gxv[i]) * gyp;

            const bool sn = gy < 0.0f;
            float gg  = sn ? -gx : gx;
            float sgn = sn ? -1.0f : 1.0f;
            float ay  = fabsf(gy);
            const bool pA = gg > 0.0f;
            const bool pD = ay < gg;       // pD => pA
            const bool pS = ay > -gg;      // pA => pS

            float w0 = pD         ? w : 0.0f;
            float w1 = (pA != pD) ? w : 0.0f;
            float w2 = (pA != pS) ? w : 0.0f;
            float w3 = !pS        ? w : 0.0f;
            hs[0] += w0;  hd[0] = fmaf(sgn, w0, hd[0]);
            hs[1] += w1;  hd[1] = fmaf(sgn, w1, hd[1]);
            hs[2] += w2;  hd[2] = fmaf(sgn, w2, hd[2]);
            hs[3] += w3;  hd[3] = fmaf(sgn, w3, hd[3]);

            ta[i] = tb[i]; tb[i] = tc[i];
            da[i] = db[i]; db[i] = dc[i];
        }
    }

    // ---- Pair fold: the 2 half-cell threads are adjacent lanes (cg even/odd) ----
#pragma unroll
    for (int k = 0; k < 4; k++) {
        hs[k] += __shfl_xor_sync(0xffffffffu, hs[k], 1);
        hd[k] += __shfl_xor_sync(0xffffffffu, hd[k], 1);
    }
    // even lane: bins 0-3 = 0.5*(hs+hd); odd lane: bins 4-7 = 0.5*(hs-hd)
    const float hsgn = oddh ? -0.5f : 0.5f;
    float4 res;
    res.x = fmaf(hsgn, hd[0], 0.5f * hs[0]);
    res.y = fmaf(hsgn, hd[1], 0.5f * hs[1]);
    res.z = fmaf(hsgn, hd[2], 0.5f * hs[2]);
    res.w = fmaf(hsgn, hd[3], 0.5f * hs[3]);

    // out[b][ cell_y=(s*4+cr), cell_x=(cg>>1) ][ bins ]
    float* op = out + (size_t)b * FEAT
              + ((size_t)((s * 4 + cr) * HC + (cg >> 1))) * NBINS + (oddh ? 4 : 0);
    *(float4*)op = res;

    float ssq = fmaf(res.x, res.x, fmaf(res.y, res.y, fmaf(res.z, res.z, res.w * res.w)));

    // Block sum of squares -> deterministic per-strip partial
#pragma unroll
    for (int o = 16; o > 0; o >>= 1)
        ssq += __shfl_xor_sync(0xffffffffu, ssq, o);
    if (lane == 0) wsum[warp] = ssq;
    __syncthreads();
    if (tid == 0) {
        float t = 0.0f;
#pragma unroll
        for (int w = 0; w < NTH / 32; w++) t += wsum[w];
        g_partial[b * NSTRIPS + s] = t;
    }

    // ---- Fused normalization: last arriving block for image b scales it ----
    __threadfence();
    if (tid == 0) s_arrive = atomicAdd(&g_count[b], 1u);
    __syncthreads();
    if (s_arrive == NSTRIPS - 1) {
        __threadfence();
        if (tid == 0) {
            float t = 0.0f;
#pragma unroll
            for (int i = 0; i < NSTRIPS; i++) t += g_partial[b * NSTRIPS + i];
            s_inv = 1.0f / (sqrtf(t) + 1e-6f);
            g_count[b] = 0;                // restore for next launch / replay
        }
        __syncthreads();
        const float inv = s_inv;
        float4* o4 = (float4*)(out + (size_t)b * FEAT);
#pragma unroll
        for (int i = 0; i < FEAT / 4 / NTH; i++) {   // 7 iterations
            float4 v = o4[i * NTH + tid];
            v.x *= inv; v.y *= inv; v.z *= inv; v.w *= inv;
            o4[i * NTH + tid] = v;
        }
    }
}

extern "C" void kernel_launch(void* const* d_in, const int* in_sizes, int n_in,
                              void* d_out, int out_size) {
    const float* x = (const float*)d_in[0];
    float* out = (float*)d_out;

    const int bs = in_sizes[0] / (3 * IMG * IMG);

    dim3 grid(NSTRIPS, bs);
    hog_kernel<<<grid, NTH>>>(x, out);
}

// round 10
// speedup vs baseline: 1.1933x; 1.1933x over previous
#include <cuda_runtime.h>

#define IMG 224
#define CS 8
#define NBINS 8
#define HC 28                      // cells per dim
#define FEAT (HC * HC * NBINS)     // 6272 per image
#define SROWS 16                   // pixel rows per strip
#define NSTRIPS (IMG / SROWS)      // 14
#define LROWS (SROWS + 2)          // 18 gray rows incl vertical halo
#define SSTRIDE 232                // smem row stride (floats)
#define NTH 224                    // one thread per column
#define ROW4 (IMG / 4)             // 56 float4 per image row
#define MAXB 1024

// Gaussian (SIGMA=1, CS=8) separable: g[p][c] = GY(p)*GX(c), coords p-3.5
#define GW3 0.0021874911f          // exp(-6.125)
#define GW2 0.0439369336f          // exp(-3.125)
#define GW1 0.3246524674f          // exp(-1.125)
#define GW0 0.8824969026f          // exp(-0.125)
#define GY(p) (((p)==0||(p)==7) ? GW3 : ((p)==1||(p)==6) ? GW2 : ((p)==2||(p)==5) ? GW1 : GW0)

__device__ float        g_partial[MAXB * NSTRIPS];  // per (image, strip) sum of squares
__device__ unsigned int g_count[MAXB];              // zero-init; restored to 0 every call

__global__ void __launch_bounds__(NTH, 9)
hog_kernel(const float* __restrict__ x,
           float* __restrict__ out) {
    const int s   = blockIdx.x;     // strip
    const int b   = blockIdx.y;     // image
    const int tid = threadIdx.x;
    const int lane = tid & 31;
    const int warp = tid >> 5;

    __shared__ float sgray[LROWS * SSTRIDE];
    __shared__ float wsum[NTH / 32];
    __shared__ unsigned int s_arrive;
    __shared__ float s_inv;

    // Zero side padding: only cols 3 and 228 of each row are ever read as halo
    if (tid < LROWS) {
        sgray[tid * SSTRIDE + 3]   = 0.0f;
        sgray[tid * SSTRIDE + 228] = 0.0f;
    }

    // ---- Gray fill: statically unrolled, predicated iterations (front-batched LDG) ----
    const float* xb  = x + (size_t)b * 3 * IMG * IMG;
    const int    gr0 = s * SROWS - 1;
    {
        const int r0 = tid / ROW4;       // 0..3
        const int q  = tid - r0 * ROW4;  // 0..55
        if (s != 0 && s != NSTRIPS - 1) {
            // interior strip: all rows in-bounds, unconditional loads
#pragma unroll
            for (int it = 0; it < 5; it++) {
                const int rr = r0 + it * 4;
                if (rr < LROWS) {
                    const float* base = xb + (gr0 + rr) * IMG + q * 4;
                    float4 r4 = *(const float4*)(base);
                    float4 g4 = *(const float4*)(base + IMG * IMG);
                    float4 b4 = *(const float4*)(base + 2 * IMG * IMG);
                    float4 o;
                    o.x = fmaf(0.2989f, r4.x, fmaf(0.587f, g4.x, 0.114f * b4.x));
                    o.y = fmaf(0.2989f, r4.y, fmaf(0.587f, g4.y, 0.114f * b4.y));
                    o.z = fmaf(0.2989f, r4.z, fmaf(0.587f, g4.z, 0.114f * b4.z));
                    o.w = fmaf(0.2989f, r4.w, fmaf(0.587f, g4.w, 0.114f * b4.w));
                    *(float4*)(sgray + rr * SSTRIDE + 4 + q * 4) = o;
                }
            }
        } else {
#pragma unroll
            for (int it = 0; it < 5; it++) {
                const int rr = r0 + it * 4;
                if (rr < LROWS) {
                    const int gr = gr0 + rr;
                    float4 o = make_float4(0.f, 0.f, 0.f, 0.f);
                    if (gr >= 0 && gr < IMG) {
                        const float* base = xb + gr * IMG + q * 4;
                        float4 r4 = *(const float4*)(base);
                        float4 g4 = *(const float4*)(base + IMG * IMG);
                        float4 b4 = *(const float4*)(base + 2 * IMG * IMG);
                        o.x = fmaf(0.2989f, r4.x, fmaf(0.587f, g4.x, 0.114f * b4.x));
                        o.y = fmaf(0.2989f, r4.y, fmaf(0.587f, g4.y, 0.114f * b4.y));
                        o.z = fmaf(0.2989f, r4.z, fmaf(0.587f, g4.z, 0.114f * b4.z));
                        o.w = fmaf(0.2989f, r4.w, fmaf(0.587f, g4.w, 0.114f * b4.w));
                    }
                    *(float4*)(sgray + rr * SSTRIDE + 4 + q * 4) = o;
                }
            }
        }
    }
    __syncthreads();

    // One thread per column: separable Sobel with rolling rows.
    const float* col = sgray + tid + 4;

    // Column Gaussian factor (folded into reconstruct): hg = 0.5 * GX(tid&7)
    const int c7 = tid & 7;
    const int dc = min(c7, 7 - c7);    // 0..3
    const float gxc = (dc == 3) ? GW0 : (dc == 2) ? GW1 : (dc == 1) ? GW2 : GW3;
    const float hg = 0.5f * gxc;

    float t0, t1, d0, d1;
    {
        float a = col[-1], m = col[0], z = col[1];
        t0 = fmaf(2.0f, m, a + z);  d0 = z - a;
        a = col[SSTRIDE - 1]; m = col[SSTRIDE]; z = col[SSTRIDE + 1];
        t1 = fmaf(2.0f, m, a + z);  d1 = z - a;
    }

    float ssq = 0.0f;
    float* ob = out + (size_t)b * FEAT + s * 2 * 224;

#pragma unroll
    for (int half = 0; half < 2; half++) {
        // Quadrant-fold histogram: hs[j] = sum of w in class j (both gy signs),
        // hd[j] = signed sum (+w for gy>=0, -w for gy<0).
        float hs[4], hd[4];
#pragma unroll
        for (int k = 0; k < 4; k++) { hs[k] = 0.0f; hd[k] = 0.0f; }

#pragma unroll
        for (int p = 0; p < 8; p++) {
            const int rr = half * 8 + p + 2;
            float a = col[rr * SSTRIDE - 1];
            float m = col[rr * SSTRIDE];
            float z = col[rr * SSTRIDE + 1];
            float t2 = fmaf(2.0f, m, a + z);
            float d2 = z - a;

            float gx = fmaf(2.0f, d1, d0) + d2;
            float gy = t2 - t0;

            float s2 = fmaf(gy, gy, fmaf(gx, gx, 1e-6f));
            float mag;
            asm("sqrt.approx.f32 %0, %1;" : "=f"(mag) : "f"(s2));
            float w = mag * GY(p);     // compile-time immediate multiplier

            // classify on (gx2, |gy|) upper half-plane; sn = which gy half
            const bool sn  = gy < 0.0f;
            float gx2 = sn ? -gx : gx;
            float sgn = sn ? -1.0f : 1.0f;
            float ay  = fabsf(gy);
            const bool pA = gx2 > 0.0f;
            const bool pD = ay < gx2;      // pD => pA
            const bool pS = ay > -gx2;     // pA => pS

            float w0 = pD         ? w : 0.0f;
            float w1 = (pA != pD) ? w : 0.0f;
            float w2 = (pA != pS) ? w : 0.0f;
            float w3 = !pS        ? w : 0.0f;
            hs[0] += w0;  hd[0] = fmaf(sgn, w0, hd[0]);
            hs[1] += w1;  hd[1] = fmaf(sgn, w1, hd[1]);
            hs[2] += w2;  hd[2] = fmaf(sgn, w2, hd[2]);
            hs[3] += w3;  hd[3] = fmaf(sgn, w3, hd[3]);

            t0 = t1; t1 = t2; d0 = d1; d1 = d2;
        }

        // Reconstruct 8 bins with column-Gaussian folded in
        float h[NBINS];
#pragma unroll
        for (int k = 0; k < 4; k++) {
            float e = hg * hs[k];
            h[k]     = fmaf( hg, hd[k], e);
            h[k + 4] = fmaf(-hg, hd[k], e);
        }

        // 8-lane multi-bin fold: within each 8-lane cell group, lane ends with bin = lane&7
        const bool q4 = (lane & 4) != 0;
        float s0 = q4 ? h[0] : h[4];
        float s1 = q4 ? h[1] : h[5];
        float s2_ = q4 ? h[2] : h[6];
        float s3 = q4 ? h[3] : h[7];
        float a0 = (q4 ? h[4] : h[0]) + __shfl_xor_sync(0xffffffffu, s0, 4);
        float a1 = (q4 ? h[5] : h[1]) + __shfl_xor_sync(0xffffffffu, s1, 4);
        float a2 = (q4 ? h[6] : h[2]) + __shfl_xor_sync(0xffffffffu, s2_, 4);
        float a3 = (q4 ? h[7] : h[3]) + __shfl_xor_sync(0xffffffffu, s3, 4);

        const bool q2 = (lane & 2) != 0;
        float u0 = q2 ? a0 : a2;
        float u1 = q2 ? a1 : a3;
        float c0 = (q2 ? a2 : a0) + __shfl_xor_sync(0xffffffffu, u0, 2);
        float c1 = (q2 ? a3 : a1) + __shfl_xor_sync(0xffffffffu, u1, 2);

        const bool q1 = (lane & 1) != 0;
        float v_ = q1 ? c0 : c1;
        float dsum = (q1 ? c1 : c0) + __shfl_xor_sync(0xffffffffu, v_, 1);

        // Coalesced: out[b][ (s*2+half)*28 + tid/8 ][ tid&7 ]
        ob[half * 224 + tid] = dsum;
        ssq = fmaf(dsum, dsum, ssq);
    }

    // Block sum of squares -> deterministic per-strip partial
#pragma unroll
    for (int o = 16; o > 0; o >>= 1)
        ssq += __shfl_xor_sync(0xffffffffu, ssq, o);
    if (lane == 0) wsum[warp] = ssq;
    __syncthreads();
    if (tid == 0) {
        float t = 0.0f;
#pragma unroll
        for (int w = 0; w < NTH / 32; w++) t += wsum[w];
        g_partial[b * NSTRIPS + s] = t;
    }

    // ---- Fused normalization: last arriving block for image b scales it ----
    __threadfence();                       // publish out rows + g_partial
    if (tid == 0) s_arrive = atomicAdd(&g_count[b], 1u);
    __syncthreads();
    if (s_arrive == NSTRIPS - 1) {
        __threadfence();                   // acquire other strips' writes
        if (tid == 0) {
            float t = 0.0f;
#pragma unroll
            for (int i = 0; i < NSTRIPS; i++) t += g_partial[b * NSTRIPS + i];
            s_inv = 1.0f / (sqrtf(t) + 1e-6f);
            g_count[b] = 0;                // restore for next launch / replay
        }
        __syncthreads();
        const float inv = s_inv;
        float4* o4 = (float4*)(out + (size_t)b * FEAT);
#pragma unroll
        for (int i = 0; i < FEAT / 4 / NTH; i++) {   // 7 iterations
            float4 v = o4[i * NTH + tid];
            v.x *= inv; v.y *= inv; v.z *= inv; v.w *= inv;
            o4[i * NTH + tid] = v;
        }
    }
}

extern "C" void kernel_launch(void* const* d_in, const int* in_sizes, int n_in,
                              void* d_out, int out_size) {
    const float* x = (const float*)d_in[0];
    float* out = (float*)d_out;

    const int bs = in_sizes[0] / (3 * IMG * IMG);

    dim3 grid(NSTRIPS, bs);
    hog_kernel<<<grid, NTH>>>(x, out);
}